// round 8
// baseline (speedup 1.0000x reference)
#include <cuda_runtime.h>
#include <cstdint>

// VQ nearest-codebook argmin, exact fp32:
//   d_k = (||z||^2 - 2 z.c_k) + ||c_k||^2 ; argmin_k, first-index ties.
// N = 131072 rows, D = 64, K = 512.
//
// Round-8: OUTPUT WRITTEN AS FLOAT32 VALUES. Diagnosis: rel_err stuck at
// exactly 1.000000 across 7 rounds == comparison sees an all-(approx)zero
// output == my int32/int64 index bit patterns (0..511) reinterpreted as
// f32 denormals ~5e-43. The harness's __output__ dtype is float32, so
// indices must be written as float VALUES: out[row] = (float)bidx.
// Indices 0..511 are exactly representable in f32 -> rel_err 0 if argmin
// is exact.
//
// Compute path unchanged (exonerated): static smem only, plain fmaf,
// codebook in 4 x 128-code chunks, broadcast LDS, 4 FFMA chains.

#define NROWS  131072
#define KCODES 512
#define DIM    64
#define CHUNK  128
#define NCHUNK (KCODES / CHUNK)
#define TPB    256
#define GRID   (NROWS / TPB)     // 512, exact

__global__ void __launch_bounds__(TPB)
vq_argmin_kernel(const float* __restrict__ z, const float* __restrict__ cb,
                 float* __restrict__ out)
{
    __shared__ float s_cb[CHUNK * DIM];   // 32 KB
    __shared__ float s_c2[CHUNK];

    const int row = blockIdx.x * TPB + threadIdx.x;   // < 131072 always

    // Row into registers (64 floats, 256B, aligned).
    float zr[DIM];
    {
        const float4* zp = (const float4*)(z + (size_t)row * DIM);
        #pragma unroll
        for (int i = 0; i < DIM / 4; i++) {
            float4 v = zp[i];
            zr[4 * i]     = v.x;
            zr[4 * i + 1] = v.y;
            zr[4 * i + 2] = v.z;
            zr[4 * i + 3] = v.w;
        }
    }

    // S = ||z||^2 (two chains).
    float s0 = 0.f, s1 = 0.f;
    #pragma unroll
    for (int i = 0; i < DIM; i += 2) {
        s0 = fmaf(zr[i],     zr[i],     s0);
        s1 = fmaf(zr[i + 1], zr[i + 1], s1);
    }
    const float S = s0 + s1;

    float best = 3.4e38f;
    int bidx = 0;

    for (int ch = 0; ch < NCHUNK; ch++) {
        __syncthreads();                      // previous chunk fully consumed
        // Stage this 128-code chunk (32KB) into smem.
        {
            const float4* g4 = (const float4*)(cb + (size_t)ch * CHUNK * DIM);
            float4* s4 = (float4*)s_cb;
            #pragma unroll 4
            for (int i = threadIdx.x; i < CHUNK * DIM / 4; i += TPB)
                s4[i] = g4[i];
        }
        __syncthreads();
        // ||c||^2 for this chunk.
        for (int k = threadIdx.x; k < CHUNK; k += TPB) {
            const float* c = s_cb + k * DIM;
            float s = 0.f;
            #pragma unroll
            for (int d = 0; d < DIM; d++) s = fmaf(c[d], c[d], s);
            s_c2[k] = s;
        }
        __syncthreads();

        // Scan 128 codes, 4 at a time (4 independent FFMA chains).
        const int kbase = ch * CHUNK;
        for (int k = 0; k < CHUNK; k += 4) {
            const float4* c0 = (const float4*)(s_cb + (k    ) * DIM);
            const float4* c1 = (const float4*)(s_cb + (k + 1) * DIM);
            const float4* c2 = (const float4*)(s_cb + (k + 2) * DIM);
            const float4* c3 = (const float4*)(s_cb + (k + 3) * DIM);
            float a0 = 0.f, a1 = 0.f, a2 = 0.f, a3 = 0.f;
            #pragma unroll
            for (int i = 0; i < DIM / 4; i++) {    // 16 iters, broadcast LDS.128
                float4 v0 = c0[i];
                float4 v1 = c1[i];
                float4 v2 = c2[i];
                float4 v3 = c3[i];
                float x0 = zr[4 * i], x1 = zr[4 * i + 1];
                float x2 = zr[4 * i + 2], x3 = zr[4 * i + 3];
                a0 = fmaf(x0, v0.x, a0); a0 = fmaf(x1, v0.y, a0);
                a0 = fmaf(x2, v0.z, a0); a0 = fmaf(x3, v0.w, a0);
                a1 = fmaf(x0, v1.x, a1); a1 = fmaf(x1, v1.y, a1);
                a1 = fmaf(x2, v1.z, a1); a1 = fmaf(x3, v1.w, a1);
                a2 = fmaf(x0, v2.x, a2); a2 = fmaf(x1, v2.y, a2);
                a2 = fmaf(x2, v2.z, a2); a2 = fmaf(x3, v2.w, a2);
                a3 = fmaf(x0, v3.x, a3); a3 = fmaf(x1, v3.y, a3);
                a3 = fmaf(x2, v3.z, a3); a3 = fmaf(x3, v3.w, a3);
            }
            // Reference formula incl. the large S term: its fp32 rounding at
            // magnitude ~64 defines the argmin ordering (and tie grid).
            float d0 = (S - 2.0f * a0) + s_c2[k];
            float d1 = (S - 2.0f * a1) + s_c2[k + 1];
            float d2 = (S - 2.0f * a2) + s_c2[k + 2];
            float d3 = (S - 2.0f * a3) + s_c2[k + 3];
            if (d0 < best) { best = d0; bidx = kbase + k;     }
            if (d1 < best) { best = d1; bidx = kbase + k + 1; }
            if (d2 < best) { best = d2; bidx = kbase + k + 2; }
            if (d3 < best) { best = d3; bidx = kbase + k + 3; }
        }
    }

    // FLOAT-VALUED index write (output dtype is float32).
    out[row] = (float)bidx;
}

extern "C" void kernel_launch(void* const* d_in, const int* in_sizes, int n_in,
                              void* d_out, int out_size)
{
    // Robust input classification by size VALUE (covers both orders and
    // both units; all four candidate values are pairwise distinct):
    //   codebook: 32768 elem / 131072 B ; z_e_x: 8388608 elem / 33554432 B
    const float* z  = nullptr;
    const float* cb = nullptr;
    for (int i = 0; i < n_in; i++) {
        const int s = in_sizes[i];
        if (s == 32768 || s == 131072)            cb = (const float*)d_in[i];
        else if (s == 8388608 || s == 33554432)   z  = (const float*)d_in[i];
    }
    if (!z || !cb) {                 // fallback: declaration order z, codebook
        z  = (const float*)d_in[0];
        cb = (const float*)d_in[n_in > 1 ? 1 : 0];
    }

    vq_argmin_kernel<<<GRID, TPB>>>(z, cb, (float*)d_out);
}

// round 9
// speedup vs baseline: 1.3616x; 1.3616x over previous
#include <cuda_runtime.h>
#include <cstdint>

// VQ nearest-codebook argmin, exact fp32:
//   d_k = (||z||^2 - 2 z.c_k) + ||c_k||^2 ; argmin_k, first-index ties.
// N = 131072 rows, D = 64, K = 512. OUTPUT = float32 index values
// (round-8 finding; indices 0..511 exact in f32).
//
// Round-9 optimization (baseline 332.7us was L1-bound: LDS 78%, fma 37%):
//  - 2 rows per thread: each codebook LDS.128 now feeds 2 rows
//    -> LDS instruction count halved -> L1 busy ~135us.
//  - packed fma.rn.f32x2: FMA issue count halved -> FFMA2 floor ~120us.
//  - 16 independent packed accumulator chains/thread cover FFMA latency
//    at the reduced occupancy (regs ~175, TPB=128).
// Codebook still staged in 4 x 128-code static-smem chunks; warp lanes
// scan the same code => broadcast LDS (conflict-free).

#define NROWS  131072
#define KCODES 512
#define DIM    64
#define CHUNK  128
#define NCHUNK (KCODES / CHUNK)
#define TPB    128
#define RPT    2                    // rows per thread
#define RPB    (TPB * RPT)          // 256 rows per block
#define GRID   (NROWS / RPB)        // 512, exact

typedef unsigned long long u64;

__device__ __forceinline__ u64 fma2(u64 a, u64 b, u64 c) {
    u64 d;
    asm("fma.rn.f32x2 %0, %1, %2, %3;" : "=l"(d) : "l"(a), "l"(b), "l"(c));
    return d;
}
__device__ __forceinline__ float hsum2(u64 v) {
    float lo, hi;
    asm("mov.b64 {%0, %1}, %2;" : "=f"(lo), "=f"(hi) : "l"(v));
    return lo + hi;
}

__global__ void __launch_bounds__(TPB)
vq_argmin_kernel(const float* __restrict__ z, const float* __restrict__ cb,
                 float* __restrict__ out)
{
    __shared__ float s_cb[CHUNK * DIM];   // 32 KB
    __shared__ float s_c2[CHUNK];

    const int row0 = blockIdx.x * RPB + threadIdx.x;   // coalesced row set 0
    const int row1 = row0 + TPB;                        // coalesced row set 1

    // Two rows into registers as packed f32x2 (32 u64 each).
    u64 za[DIM / 2], zb[DIM / 2];
    {
        const ulonglong2* pa = (const ulonglong2*)(z + (size_t)row0 * DIM);
        const ulonglong2* pb = (const ulonglong2*)(z + (size_t)row1 * DIM);
        #pragma unroll
        for (int i = 0; i < DIM / 4; i++) {
            ulonglong2 va = pa[i];
            za[2 * i] = va.x; za[2 * i + 1] = va.y;
            ulonglong2 vb = pb[i];
            zb[2 * i] = vb.x; zb[2 * i + 1] = vb.y;
        }
    }

    // S_r = ||z_r||^2 (packed, 2 chains each).
    float S0, S1;
    {
        u64 a0 = 0, a1 = 0, b0 = 0, b1 = 0;
        #pragma unroll
        for (int i = 0; i < DIM / 2; i += 2) {
            a0 = fma2(za[i], za[i], a0);
            a1 = fma2(za[i + 1], za[i + 1], a1);
            b0 = fma2(zb[i], zb[i], b0);
            b1 = fma2(zb[i + 1], zb[i + 1], b1);
        }
        S0 = hsum2(a0) + hsum2(a1);
        S1 = hsum2(b0) + hsum2(b1);
    }

    float best0 = 3.4e38f, best1 = 3.4e38f;
    int bidx0 = 0, bidx1 = 0;

    for (int ch = 0; ch < NCHUNK; ch++) {
        __syncthreads();                      // previous chunk fully consumed
        // Stage this 128-code chunk (32KB) into smem.
        {
            const float4* g4 = (const float4*)(cb + (size_t)ch * CHUNK * DIM);
            float4* s4 = (float4*)s_cb;
            #pragma unroll 4
            for (int i = threadIdx.x; i < CHUNK * DIM / 4; i += TPB)
                s4[i] = g4[i];
        }
        __syncthreads();
        // ||c||^2 for this chunk.
        for (int k = threadIdx.x; k < CHUNK; k += TPB) {
            const float* c = s_cb + k * DIM;
            float s = 0.f;
            #pragma unroll
            for (int d = 0; d < DIM; d++) s = fmaf(c[d], c[d], s);
            s_c2[k] = s;
        }
        __syncthreads();

        const int kbase = ch * CHUNK;
        // 4 codes x 2 rows per iteration: 8 packed accum chains,
        // 4 LDS.128 : 16 FFMA2 per i-step (each load feeds both rows).
        for (int k = 0; k < CHUNK; k += 4) {
            const ulonglong2* c0 = (const ulonglong2*)(s_cb + (k    ) * DIM);
            const ulonglong2* c1 = (const ulonglong2*)(s_cb + (k + 1) * DIM);
            const ulonglong2* c2 = (const ulonglong2*)(s_cb + (k + 2) * DIM);
            const ulonglong2* c3 = (const ulonglong2*)(s_cb + (k + 3) * DIM);
            u64 A00 = 0, A01 = 0, A02 = 0, A03 = 0;   // row0 x codes 0..3
            u64 A10 = 0, A11 = 0, A12 = 0, A13 = 0;   // row1 x codes 0..3
            #pragma unroll
            for (int i = 0; i < DIM / 4; i++) {       // 16 iters
                ulonglong2 v0 = c0[i];                // broadcast LDS.128
                ulonglong2 v1 = c1[i];
                ulonglong2 v2 = c2[i];
                ulonglong2 v3 = c3[i];
                u64 xa0 = za[2 * i], xa1 = za[2 * i + 1];
                u64 xb0 = zb[2 * i], xb1 = zb[2 * i + 1];
                A00 = fma2(xa0, v0.x, A00); A00 = fma2(xa1, v0.y, A00);
                A01 = fma2(xa0, v1.x, A01); A01 = fma2(xa1, v1.y, A01);
                A02 = fma2(xa0, v2.x, A02); A02 = fma2(xa1, v2.y, A02);
                A03 = fma2(xa0, v3.x, A03); A03 = fma2(xa1, v3.y, A03);
                A10 = fma2(xb0, v0.x, A10); A10 = fma2(xb1, v0.y, A10);
                A11 = fma2(xb0, v1.x, A11); A11 = fma2(xb1, v1.y, A11);
                A12 = fma2(xb0, v2.x, A12); A12 = fma2(xb1, v2.y, A12);
                A13 = fma2(xb0, v3.x, A13); A13 = fma2(xb1, v3.y, A13);
            }
            const float q0 = s_c2[k], q1 = s_c2[k + 1];
            const float q2 = s_c2[k + 2], q3 = s_c2[k + 3];
            // Reference formula incl. the large S term; fp32 rounding at
            // magnitude ~64 defines the argmin ordering (round-8 verified
            // order-robust: rel_err == 0).
            float d00 = (S0 - 2.0f * hsum2(A00)) + q0;
            float d01 = (S0 - 2.0f * hsum2(A01)) + q1;
            float d02 = (S0 - 2.0f * hsum2(A02)) + q2;
            float d03 = (S0 - 2.0f * hsum2(A03)) + q3;
            float d10 = (S1 - 2.0f * hsum2(A10)) + q0;
            float d11 = (S1 - 2.0f * hsum2(A11)) + q1;
            float d12 = (S1 - 2.0f * hsum2(A12)) + q2;
            float d13 = (S1 - 2.0f * hsum2(A13)) + q3;
            if (d00 < best0) { best0 = d00; bidx0 = kbase + k;     }
            if (d01 < best0) { best0 = d01; bidx0 = kbase + k + 1; }
            if (d02 < best0) { best0 = d02; bidx0 = kbase + k + 2; }
            if (d03 < best0) { best0 = d03; bidx0 = kbase + k + 3; }
            if (d10 < best1) { best1 = d10; bidx1 = kbase + k;     }
            if (d11 < best1) { best1 = d11; bidx1 = kbase + k + 1; }
            if (d12 < best1) { best1 = d12; bidx1 = kbase + k + 2; }
            if (d13 < best1) { best1 = d13; bidx1 = kbase + k + 3; }
        }
    }

    out[row0] = (float)bidx0;     // float-valued indices (output dtype f32)
    out[row1] = (float)bidx1;
}

extern "C" void kernel_launch(void* const* d_in, const int* in_sizes, int n_in,
                              void* d_out, int out_size)
{
    // Robust input classification by size value (both orders, both units).
    const float* z  = nullptr;
    const float* cb = nullptr;
    for (int i = 0; i < n_in; i++) {
        const int s = in_sizes[i];
        if (s == 32768 || s == 131072)            cb = (const float*)d_in[i];
        else if (s == 8388608 || s == 33554432)   z  = (const float*)d_in[i];
    }
    if (!z || !cb) {
        z  = (const float*)d_in[0];
        cb = (const float*)d_in[n_in > 1 ? 1 : 0];
    }

    vq_argmin_kernel<<<GRID, TPB>>>(z, cb, (float*)d_out);
}